// round 5
// baseline (speedup 1.0000x reference)
#include <cuda_runtime.h>
#include <math.h>

// ---------------------------------------------------------------------------
// CircleLoss forward, B=8192, D=1024, N_IDS=512. Fully fused:
//   normalize -> triangular GEMM with in-tile LSE epilogue -> per-row combine.
// LSE uses data-independent fixed maxima (valid for any cosine sims):
//   logit_n in [-4, 60]  -> fp32 exp(l - 60), no under/overflow possible
//   logit_p in [-4, 252] -> fp64 exp(l - 128), range e^-132..e^124, safe
// No sim matrix is ever materialized. All reductions deterministic.
// ---------------------------------------------------------------------------

#define NB 8192
#define ND 1024
#define NT 64              // number of 128-wide tiles = NB/128

__device__ float  g_xn[NB * ND];            // normalized inputs (32 MB)
__device__ float  g_part_n[NB * NT];        // per (row, coltile) neg partial (2 MB)
__device__ double g_part_p[NB * NT];        // per (row, coltile) pos partial (4 MB)
__device__ float  g_loss[NB];
__device__ int    g_valid[NB];
__device__ int    g_tgt[NB];
__device__ int    g_hist[512];
__device__ int    g_is64;

// ---- packed f32x2 helpers (FFMA2: 2 MACs per fma-pipe issue on sm_103a) ----
__device__ __forceinline__ unsigned long long pack2(float lo, float hi) {
    unsigned long long r;
    asm("mov.b64 %0, {%1, %2};" : "=l"(r) : "f"(lo), "f"(hi));
    return r;
}
__device__ __forceinline__ void unpack2(unsigned long long v, float& lo, float& hi) {
    asm("mov.b64 {%0, %1}, %2;" : "=f"(lo), "=f"(hi) : "l"(v));
}
__device__ __forceinline__ void fma2(unsigned long long& d,
                                     unsigned long long a,
                                     unsigned long long b) {
    asm("fma.rn.f32x2 %0, %1, %2, %0;" : "+l"(d) : "l"(a), "l"(b));
}

// ---------------------------------------------------------------------------
// Kernel 0: zero the target histogram; detect targets dtype.
// Targets < 512, so an int64 LE buffer has every odd int32 word == 0.
// Reading 128 int32 words is safe under either dtype.
// ---------------------------------------------------------------------------
__global__ void detect_k(const int* __restrict__ tg32) {
    int tid = threadIdx.x;
    if (tid < 512) g_hist[tid] = 0;
    if (tid == 0) {
        int odd_or = 0;
        #pragma unroll
        for (int i = 1; i < 128; i += 2) odd_or |= tg32[i];
        g_is64 = (odd_or == 0) ? 1 : 0;
    }
}

// ---------------------------------------------------------------------------
// Kernel 1: row L2 normalize; copy targets to int32; build histogram.
// ---------------------------------------------------------------------------
__global__ __launch_bounds__(256) void normalize_k(const float* __restrict__ x,
                                                   const void* __restrict__ tg) {
    int row = blockIdx.x;
    int tid = threadIdx.x;
    float4 v = reinterpret_cast<const float4*>(x)[row * (ND / 4) + tid];
    float ss = v.x * v.x + v.y * v.y + v.z * v.z + v.w * v.w;
    #pragma unroll
    for (int o = 16; o; o >>= 1) ss += __shfl_xor_sync(0xffffffffu, ss, o);
    __shared__ float sh[8];
    if ((tid & 31) == 0) sh[tid >> 5] = ss;
    __syncthreads();
    if (tid < 32) {
        float t = (tid < 8) ? sh[tid] : 0.f;
        #pragma unroll
        for (int o = 4; o; o >>= 1) t += __shfl_xor_sync(0xffffffffu, t, o);
        if (tid == 0) sh[0] = t;
    }
    __syncthreads();
    float inv = 1.0f / fmaxf(sqrtf(sh[0]), 1e-12f);
    float4 o4 = make_float4(v.x * inv, v.y * inv, v.z * inv, v.w * inv);
    reinterpret_cast<float4*>(g_xn)[row * (ND / 4) + tid] = o4;
    if (tid == 0) {
        int t = g_is64 ? (int)((const long long*)tg)[row]
                       : ((const int*)tg)[row];
        g_tgt[row] = t;
        if ((unsigned)t < 512u) atomicAdd(&g_hist[t], 1);
    }
}

// ---------------------------------------------------------------------------
// Kernel 2: fused triangular GEMM + CircleLoss LSE epilogue.
// 128x128 tile, BK=8, 256 threads, 8x8 per thread, FFMA2 mainloop.
// Block (by,bx), bx>=by. Row-phase writes partials for rows of tile by at
// coltile bx; col-phase (bx>by) writes partials for rows of tile bx at
// coltile by (sim symmetry). Every (row, coltile) written exactly once.
// ---------------------------------------------------------------------------
__global__ __launch_bounds__(256) void gemm_k() {
    int bx = blockIdx.x;
    int by = blockIdx.y;
    if (bx < by) return;
    const int rm = by * 128, cn = bx * 128;

    __shared__ float As[8][128];
    __shared__ float Bs[8][128];
    __shared__ int sh_tr[128], sh_tc[128];
    __shared__ float  sm_f[128][17];
    __shared__ double sm_d[128][17];

    int tid = threadIdx.x;
    int lr = tid >> 1;           // 0..127 tile row loaded
    int lk = (tid & 1) << 2;     // 0 or 4
    int ty = tid >> 4;           // 0..15
    int tx = tid & 15;           // 0..15

    if (tid < 128) sh_tr[tid] = g_tgt[rm + tid];
    else           sh_tc[tid - 128] = g_tgt[cn + tid - 128];

    const float* Ap = g_xn + (size_t)(rm + lr) * ND + lk;
    const float* Bp = g_xn + (size_t)(cn + lr) * ND + lk;

    unsigned long long acc[8][4];
    #pragma unroll
    for (int i = 0; i < 8; i++)
        #pragma unroll
        for (int j = 0; j < 4; j++) acc[i][j] = 0ull;

    for (int k0 = 0; k0 < ND; k0 += 8) {
        float4 a4 = *reinterpret_cast<const float4*>(Ap + k0);
        float4 b4 = *reinterpret_cast<const float4*>(Bp + k0);
        __syncthreads();
        As[lk + 0][lr] = a4.x; As[lk + 1][lr] = a4.y;
        As[lk + 2][lr] = a4.z; As[lk + 3][lr] = a4.w;
        Bs[lk + 0][lr] = b4.x; Bs[lk + 1][lr] = b4.y;
        Bs[lk + 2][lr] = b4.z; Bs[lk + 3][lr] = b4.w;
        __syncthreads();
        #pragma unroll
        for (int k = 0; k < 8; k++) {
            float4 a0 = *reinterpret_cast<const float4*>(&As[k][ty * 8]);
            float4 a1 = *reinterpret_cast<const float4*>(&As[k][ty * 8 + 4]);
            float4 b0 = *reinterpret_cast<const float4*>(&Bs[k][tx * 8]);
            float4 b1 = *reinterpret_cast<const float4*>(&Bs[k][tx * 8 + 4]);
            unsigned long long b2[4];
            b2[0] = pack2(b0.x, b0.y); b2[1] = pack2(b0.z, b0.w);
            b2[2] = pack2(b1.x, b1.y); b2[3] = pack2(b1.z, b1.w);
            float ra[8] = {a0.x, a0.y, a0.z, a0.w, a1.x, a1.y, a1.z, a1.w};
            #pragma unroll
            for (int i = 0; i < 8; i++) {
                unsigned long long a2 = pack2(ra[i], ra[i]);
                #pragma unroll
                for (int j = 0; j < 4; j++) fma2(acc[i][j], a2, b2[j]);
            }
        }
    }

    // --- epilogue: classify, exponentiate, accumulate row/col partials ---
    float  rn_[8]; double rp_[8];   // per local row (8 rows this thread)
    float  cf_[8]; double cd_[8];   // per local col (8 cols this thread)
    int tr_[8], tc_[8];
    #pragma unroll
    for (int i = 0; i < 8; i++) {
        rn_[i] = 0.f; rp_[i] = 0.0; cf_[i] = 0.f; cd_[i] = 0.0;
        tr_[i] = sh_tr[ty * 8 + i];
        tc_[i] = sh_tc[tx * 8 + i];
    }

    #pragma unroll
    for (int i = 0; i < 8; i++) {
        int gi = rm + ty * 8 + i;
        #pragma unroll
        for (int j4 = 0; j4 < 4; j4++) {
            float sv[2];
            unpack2(acc[i][j4], sv[0], sv[1]);
            #pragma unroll
            for (int u = 0; u < 2; u++) {
                int jj = j4 * 2 + u;
                int gj = cn + tx * 8 + jj;
                float s = sv[u];
                if (gi != gj) {
                    if (tr_[i] == tc_[jj]) {
                        // positive pair: fp64 exp around fixed max 128
                        float lp = -fmaxf(1.25f - s, 0.f) * (s - 0.75f) * 64.f;
                        double e = exp((double)lp - 128.0);
                        rp_[i] += e; cd_[jj] += e;
                    } else {
                        // negative pair: fp32 exp around fixed max 60
                        float ln_ = fmaxf(s + 0.25f, 0.f) * (s - 0.25f) * 64.f;
                        float e = __expf(ln_ - 60.f);
                        rn_[i] += e; cf_[jj] += e;
                    }
                }
            }
        }
    }

    // Row-phase fp32: partials for rows rm+t at coltile bx.
    __syncthreads();
    #pragma unroll
    for (int i = 0; i < 8; i++) sm_f[ty * 8 + i][tx] = rn_[i];
    __syncthreads();
    if (tid < 128) {
        float s = 0.f;
        #pragma unroll
        for (int k = 0; k < 16; k++) s += sm_f[tid][k];
        g_part_n[(size_t)(rm + tid) * NT + bx] = s;
    }
    __syncthreads();
    // Col-phase fp32 (mirror): partials for rows cn+t at coltile by.
    #pragma unroll
    for (int j = 0; j < 8; j++) sm_f[tx * 8 + j][ty] = cf_[j];
    __syncthreads();
    if (bx > by && tid < 128) {
        float s = 0.f;
        #pragma unroll
        for (int k = 0; k < 16; k++) s += sm_f[tid][k];
        g_part_n[(size_t)(cn + tid) * NT + by] = s;
    }
    __syncthreads();
    // Row-phase fp64.
    #pragma unroll
    for (int i = 0; i < 8; i++) sm_d[ty * 8 + i][tx] = rp_[i];
    __syncthreads();
    if (tid < 128) {
        double s = 0.0;
        #pragma unroll
        for (int k = 0; k < 16; k++) s += sm_d[tid][k];
        g_part_p[(size_t)(rm + tid) * NT + bx] = s;
    }
    __syncthreads();
    // Col-phase fp64.
    #pragma unroll
    for (int j = 0; j < 8; j++) sm_d[tx * 8 + j][ty] = cd_[j];
    __syncthreads();
    if (bx > by && tid < 128) {
        double s = 0.0;
        #pragma unroll
        for (int k = 0; k < 16; k++) s += sm_d[tid][k];
        g_part_p[(size_t)(cn + tid) * NT + by] = s;
    }
}

// ---------------------------------------------------------------------------
// Kernel 3: per-row combine (deterministic fixed-order), softplus, validity.
// One thread per row.
// ---------------------------------------------------------------------------
__global__ __launch_bounds__(256) void rowlse_k() {
    int row = blockIdx.x * 256 + threadIdx.x;
    float sn = 0.f;
    #pragma unroll 8
    for (int k = 0; k < NT; k++) sn += g_part_n[(size_t)row * NT + k];
    double sp = 0.0;
    #pragma unroll 8
    for (int k = 0; k < NT; k++) sp += g_part_p[(size_t)row * NT + k];

    int t = g_tgt[row];
    int c = ((unsigned)t < 512u) ? g_hist[t] : 0;
    int valid = (c >= 2) && (c < NB);

    float loss = 0.f;
    if (valid) {
        float lse_n = 60.f + logf(sn);
        float lse_p = 128.f + (float)log(sp);
        float xv = lse_n + lse_p;
        loss = fmaxf(xv, 0.f) + log1pf(expf(-fabsf(xv)));
    }
    g_loss[row] = loss;
    g_valid[row] = valid;
}

// ---------------------------------------------------------------------------
// Kernel 4: deterministic final reduction (single block).
// ---------------------------------------------------------------------------
__global__ __launch_bounds__(1024) void finalize_k(float* __restrict__ out) {
    __shared__ float sh_s[1024];
    __shared__ int sh_c[1024];
    int tid = threadIdx.x;
    float t = 0.f;
    int c = 0;
    for (int r = tid; r < NB; r += 1024) {
        t += g_loss[r];
        c += g_valid[r];
    }
    sh_s[tid] = t; sh_c[tid] = c;
    __syncthreads();
    for (int off = 512; off > 0; off >>= 1) {
        if (tid < off) {
            sh_s[tid] += sh_s[tid + off];
            sh_c[tid] += sh_c[tid + off];
        }
        __syncthreads();
    }
    if (tid == 0) {
        int cnt = sh_c[0] > 1 ? sh_c[0] : 1;
        out[0] = sh_s[0] / (float)cnt;
    }
}

// ---------------------------------------------------------------------------
extern "C" void kernel_launch(void* const* d_in, const int* in_sizes, int n_in,
                              void* d_out, int out_size) {
    const float* x = (const float*)d_in[0];
    const void* tg = d_in[1];
    float* out = (float*)d_out;

    detect_k<<<1, 512>>>((const int*)tg);
    normalize_k<<<NB, 256>>>(x, tg);
    dim3 g2(NT, NT);
    gemm_k<<<g2, 256>>>();
    rowlse_k<<<NB / 256, 256>>>();
    finalize_k<<<1, 1024>>>(out);
}

// round 7
// speedup vs baseline: 4.6473x; 4.6473x over previous
#include <cuda_runtime.h>
#include <cuda_bf16.h>
#include <math.h>
#include <stdint.h>

// ---------------------------------------------------------------------------
// CircleLoss forward, B=8192, D=1024, N_IDS=512 — mma.sync bf16 edition.
// (tcgen05 is unavailable: harness ptxas targets plain sm_103, no 'a'.)
//  1) normalize (fp32) -> bf16 matrix g_xb
//  2) triangular 128x128-tile HMMA GEMM; epilogue accumulates, for EVERY
//     off-diagonal element, exp(relu(s+.25)(s-.25)*64 - 60) (fixed-max LSE,
//     fp32-safe for all s in [-1,1]); row partials + mirrored col partials.
//  3) pos_k: per row, recompute same-target sims (fp32 dot of bf16 inputs),
//     exact lse_p, and exact correction subtracting same-target terms that
//     (2) counted as negatives.
//  4) combine: lse_n = 60 + log(sum - fix); loss = softplus(lse_n + lse_p)
// All reductions deterministic (no float atomics).
// ---------------------------------------------------------------------------

#define NB 8192
#define ND 1024
#define NT 64               // 8192 / 128 tiles

__device__ __nv_bfloat16 g_xb[NB * ND];     // 16 MB (L2-resident)
__device__ float g_part_n[NB * NT];         // 2 MB
__device__ float g_lsep[NB];
__device__ float g_negfix[NB];
__device__ float g_loss[NB];
__device__ int   g_valid[NB];
__device__ int   g_tgt[NB];
__device__ int   g_hist[512];
__device__ int   g_goff[512];
__device__ int   g_members[NB];
__device__ int   g_is64;

// ---------------- PTX helpers ----------------------------------------------
__device__ __forceinline__ uint32_t smem_u32(const void* p) {
    uint32_t a;
    asm("{ .reg .u64 t; cvta.to.shared.u64 t, %1; cvt.u32.u64 %0, t; }"
        : "=r"(a) : "l"(p));
    return a;
}
__device__ __forceinline__ void cp16(uint32_t dst, const void* src) {
    asm volatile("cp.async.cg.shared.global [%0], [%1], 16;"
                 :: "r"(dst), "l"(src) : "memory");
}
#define CP_COMMIT() asm volatile("cp.async.commit_group;" ::: "memory")
#define CP_WAIT(n)  asm volatile("cp.async.wait_group %0;" :: "n"(n) : "memory")

__device__ __forceinline__ void ldm_x4(uint32_t a, uint32_t& r0, uint32_t& r1,
                                       uint32_t& r2, uint32_t& r3) {
    asm volatile("ldmatrix.sync.aligned.m8n8.x4.shared.b16 {%0,%1,%2,%3}, [%4];"
                 : "=r"(r0), "=r"(r1), "=r"(r2), "=r"(r3) : "r"(a));
}
__device__ __forceinline__ void ldm_x2(uint32_t a, uint32_t& r0, uint32_t& r1) {
    asm volatile("ldmatrix.sync.aligned.m8n8.x2.shared.b16 {%0,%1}, [%2];"
                 : "=r"(r0), "=r"(r1) : "r"(a));
}
__device__ __forceinline__ void mma16816(float* d, const uint32_t* a,
                                         const uint32_t* b) {
    asm volatile(
        "mma.sync.aligned.m16n8k16.row.col.f32.bf16.bf16.f32 "
        "{%0,%1,%2,%3}, {%4,%5,%6,%7}, {%8,%9}, {%0,%1,%2,%3};"
        : "+f"(d[0]), "+f"(d[1]), "+f"(d[2]), "+f"(d[3])
        : "r"(a[0]), "r"(a[1]), "r"(a[2]), "r"(a[3]), "r"(b[0]), "r"(b[1]));
}

// ---------------------------------------------------------------------------
// Kernel 0: zero histogram; detect targets dtype (int64 LE has odd words 0).
// ---------------------------------------------------------------------------
__global__ void detect_k(const int* __restrict__ tg32) {
    int tid = threadIdx.x;
    if (tid < 512) g_hist[tid] = 0;
    if (tid == 0) {
        int odd_or = 0;
        #pragma unroll
        for (int i = 1; i < 128; i += 2) odd_or |= tg32[i];
        g_is64 = (odd_or == 0) ? 1 : 0;
    }
}

// ---------------------------------------------------------------------------
// Kernel 1: fp32 normalize -> bf16; targets -> int32; histogram.
// ---------------------------------------------------------------------------
__global__ __launch_bounds__(256) void normalize_k(const float* __restrict__ x,
                                                   const void* __restrict__ tg) {
    int row = blockIdx.x;
    int tid = threadIdx.x;
    float4 v = reinterpret_cast<const float4*>(x)[row * (ND / 4) + tid];
    float ss = v.x * v.x + v.y * v.y + v.z * v.z + v.w * v.w;
    #pragma unroll
    for (int o = 16; o; o >>= 1) ss += __shfl_xor_sync(0xffffffffu, ss, o);
    __shared__ float sh[8];
    if ((tid & 31) == 0) sh[tid >> 5] = ss;
    __syncthreads();
    if (tid < 32) {
        float t = (tid < 8) ? sh[tid] : 0.f;
        #pragma unroll
        for (int o = 4; o; o >>= 1) t += __shfl_xor_sync(0xffffffffu, t, o);
        if (tid == 0) sh[0] = t;
    }
    __syncthreads();
    float inv = 1.0f / fmaxf(sqrtf(sh[0]), 1e-12f);
    __nv_bfloat162 p0 = __floats2bfloat162_rn(v.x * inv, v.y * inv);
    __nv_bfloat162 p1 = __floats2bfloat162_rn(v.z * inv, v.w * inv);
    __nv_bfloat162* dst =
        reinterpret_cast<__nv_bfloat162*>(g_xb + (size_t)row * ND + tid * 4);
    dst[0] = p0; dst[1] = p1;
    if (tid == 0) {
        int t = g_is64 ? (int)((const long long*)tg)[row]
                       : ((const int*)tg)[row];
        g_tgt[row] = t;
        if ((unsigned)t < 512u) atomicAdd(&g_hist[t], 1);
    }
}

// ---------------------------------------------------------------------------
// Kernel 2: exclusive prefix sum of histogram.
// ---------------------------------------------------------------------------
__global__ void prefix_k() {
    __shared__ int sh[512];
    int t = threadIdx.x;
    sh[t] = g_hist[t];
    __syncthreads();
    for (int off = 1; off < 512; off <<= 1) {
        int v = (t >= off) ? sh[t - off] : 0;
        __syncthreads();
        sh[t] += v;
        __syncthreads();
    }
    g_goff[t] = sh[t] - g_hist[t];
}

// ---------------------------------------------------------------------------
// Kernel 3: group member lists (deterministic ballot scan). 1 block/target.
// ---------------------------------------------------------------------------
__global__ __launch_bounds__(256) void members_k() {
    int t = blockIdx.x;
    int tid = threadIdx.x, wid = tid >> 5, lane = tid & 31;
    __shared__ int wcnt[8];
    __shared__ int sbase;
    if (tid == 0) sbase = g_goff[t];
    __syncthreads();
    for (int base = 0; base < NB; base += 256) {
        bool m = (g_tgt[base + tid] == t);
        unsigned bal = __ballot_sync(0xffffffffu, m);
        if (lane == 0) wcnt[wid] = __popc(bal);
        __syncthreads();
        if (m) {
            int woff = 0;
            for (int wdx = 0; wdx < wid; wdx++) woff += wcnt[wdx];
            g_members[sbase + woff + __popc(bal & ((1u << lane) - 1u))] = base + tid;
        }
        __syncthreads();
        if (tid == 0) {
            int tot = 0;
            for (int wdx = 0; wdx < 8; wdx++) tot += wcnt[wdx];
            sbase += tot;
        }
        __syncthreads();
    }
}

// ---------------------------------------------------------------------------
// Kernel 4: HMMA triangular GEMM + negative-LSE epilogue.
// CTA tile 128x128, 8 warps (2 x 4), warp tile 64x32, BK=32, double-buffered
// cp.async. Smem rows padded to 40 halves (80 B) -> conflict-free ldmatrix.
// ---------------------------------------------------------------------------
__global__ __launch_bounds__(256) void gemm_k() {
    int bx = blockIdx.x, by = blockIdx.y;
    if (bx < by) return;
    const int rm = by * 128, cn = bx * 128;

    __shared__ __align__(16) __nv_bfloat16 sA[2][128 * 40];
    __shared__ __align__(16) __nv_bfloat16 sB[2][128 * 40];

    int tid = threadIdx.x, lane = tid & 31, wid = tid >> 5;
    int warp_m = wid >> 2, warp_n = wid & 3;

    const __nv_bfloat16* gA = g_xb + (size_t)rm * ND;
    const __nv_bfloat16* gB = g_xb + (size_t)cn * ND;
    uint32_t aSm = smem_u32(sA), bSm = smem_u32(sB);

    // copy lanes: 512 16B-chunks per tile, 2 per thread
    int ch0 = tid * 2, ch1 = tid * 2 + 1;
    int cr0 = ch0 >> 2, cs0 = ch0 & 3, cr1 = ch1 >> 2, cs1 = ch1 & 3;
    uint32_t dA0 = aSm + cr0 * 80 + cs0 * 16, dA1 = aSm + cr1 * 80 + cs1 * 16;
    uint32_t dB0 = bSm + cr0 * 80 + cs0 * 16, dB1 = bSm + cr1 * 80 + cs1 * 16;

    float acc[4][4][4];
    #pragma unroll
    for (int i = 0; i < 4; i++)
        #pragma unroll
        for (int j = 0; j < 4; j++)
            #pragma unroll
            for (int e = 0; e < 4; e++) acc[i][j][e] = 0.f;

    // ldmatrix base addresses
    uint32_t aF = aSm + ((warp_m * 64 + (lane & 15)) * 40 + (lane >> 4) * 8) * 2;
    uint32_t bF = bSm + ((warp_n * 32 + ((lane & 15) & 7)) * 40 +
                         (((lane & 15) >> 3)) * 8) * 2;

    // prefetch chunk 0
    {
        cp16(dA0, gA + (size_t)cr0 * ND + cs0 * 8);
        cp16(dA1, gA + (size_t)cr1 * ND + cs1 * 8);
        cp16(dB0, gB + (size_t)cr0 * ND + cs0 * 8);
        cp16(dB1, gB + (size_t)cr1 * ND + cs1 * 8);
        CP_COMMIT();
    }

    for (int kc = 0; kc < 32; kc++) {
        if (kc < 31) {
            uint32_t o = ((kc + 1) & 1) * 10240u;
            const __nv_bfloat16* pa = gA + (kc + 1) * 32;
            const __nv_bfloat16* pb = gB + (kc + 1) * 32;
            cp16(dA0 + o, pa + (size_t)cr0 * ND + cs0 * 8);
            cp16(dA1 + o, pa + (size_t)cr1 * ND + cs1 * 8);
            cp16(dB0 + o, pb + (size_t)cr0 * ND + cs0 * 8);
            cp16(dB1 + o, pb + (size_t)cr1 * ND + cs1 * 8);
            CP_COMMIT();
            CP_WAIT(1);
        } else {
            CP_WAIT(0);
        }
        __syncthreads();

        uint32_t bo = (kc & 1) * 10240u;
        #pragma unroll
        for (int kk = 0; kk < 2; kk++) {
            uint32_t af[4][4], bf2[4][2];
            #pragma unroll
            for (int am = 0; am < 4; am++)
                ldm_x4(aF + bo + am * 1280u + kk * 32u,
                       af[am][0], af[am][1], af[am][2], af[am][3]);
            #pragma unroll
            for (int an = 0; an < 4; an++)
                ldm_x2(bF + bo + an * 640u + kk * 32u, bf2[an][0], bf2[an][1]);
            #pragma unroll
            for (int am = 0; am < 4; am++)
                #pragma unroll
                for (int an = 0; an < 4; an++)
                    mma16816(acc[am][an], af[am], bf2[an]);
        }
        __syncthreads();
    }

    // ---- epilogue --------------------------------------------------------
    bool diag = (bx == by);
    float rsum[4][2];   // per m-atom, top/bottom row
    float csum[4][2];   // per n-atom, two cols
    #pragma unroll
    for (int a = 0; a < 4; a++) {
        rsum[a][0] = rsum[a][1] = 0.f;
        csum[a][0] = csum[a][1] = 0.f;
    }
    int lr_base = warp_m * 64;
    int lc_base = warp_n * 32;
    #pragma unroll
    for (int am = 0; am < 4; am++) {
        int r0 = lr_base + am * 16 + (lane >> 2);
        #pragma unroll
        for (int an = 0; an < 4; an++) {
            int c0 = lc_base + an * 8 + (lane & 3) * 2;
            #pragma unroll
            for (int e = 0; e < 4; e++) {
                int r = r0 + (e >> 1) * 8;
                int c = c0 + (e & 1);
                float s = acc[am][an][e];
                float ex = __expf(fmaxf(s + 0.25f, 0.f) * (s - 0.25f) * 64.f - 60.f);
                if (diag && r == c) ex = 0.f;
                rsum[am][e >> 1] += ex;
                csum[an][e & 1] += ex;
            }
        }
    }

    float* rowbuf = reinterpret_cast<float*>(sA);      // [4][128]
    float* colbuf = rowbuf + 512;                      // [2][128]

    // row reduction: sum over lane&3 (4 lanes share a row)
    #pragma unroll
    for (int am = 0; am < 4; am++)
        #pragma unroll
        for (int t = 0; t < 2; t++) {
            float v = rsum[am][t];
            v += __shfl_xor_sync(0xffffffffu, v, 1);
            v += __shfl_xor_sync(0xffffffffu, v, 2);
            if ((lane & 3) == 0)
                rowbuf[warp_n * 128 + lr_base + am * 16 + t * 8 + (lane >> 2)] = v;
        }
    // col reduction: sum over lane>>2 (8 lanes share a col)
    #pragma unroll
    for (int an = 0; an < 4; an++)
        #pragma unroll
        for (int c = 0; c < 2; c++) {
            float v = csum[an][c];
            v += __shfl_xor_sync(0xffffffffu, v, 4);
            v += __shfl_xor_sync(0xffffffffu, v, 8);
            v += __shfl_xor_sync(0xffffffffu, v, 16);
            if (lane < 4)
                colbuf[warp_m * 128 + lc_base + an * 8 + lane * 2 + c] = v;
        }
    __syncthreads();
    if (tid < 128) {
        float s = rowbuf[tid] + rowbuf[128 + tid] + rowbuf[256 + tid] + rowbuf[384 + tid];
        g_part_n[(size_t)(rm + tid) * NT + bx] = s;
        if (bx > by) {
            float cs2 = colbuf[tid] + colbuf[128 + tid];
            g_part_n[(size_t)(cn + tid) * NT + by] = cs2;
        }
    }
}

// ---------------------------------------------------------------------------
// Kernel 5: positives. One block (128 thr) per row: exact lse_p over the
// same-target group + exact negative-sum correction + validity.
// ---------------------------------------------------------------------------
__global__ __launch_bounds__(128) void pos_k() {
    int i = blockIdx.x;
    int tid = threadIdx.x, wid = tid >> 5, lane = tid & 31;
    __shared__ float wsum[4];
    __shared__ float lp_list[256];

    int t = g_tgt[i];
    int cnt = ((unsigned)t < 512u) ? g_hist[t] : 0;
    if (cnt < 2 || cnt >= NB) {
        if (tid == 0) { g_lsep[i] = 0.f; g_negfix[i] = 0.f; g_valid[i] = 0; }
        return;
    }
    float xi[8];
    {
        uint4 u = *reinterpret_cast<const uint4*>(g_xb + (size_t)i * ND + tid * 8);
        const __nv_bfloat162* p = reinterpret_cast<const __nv_bfloat162*>(&u);
        #pragma unroll
        for (int e = 0; e < 4; e++) {
            float2 f = __bfloat1622float2(p[e]);
            xi[e * 2] = f.x; xi[e * 2 + 1] = f.y;
        }
    }
    int off = g_goff[t];
    int np = 0;
    float negfix = 0.f;
    for (int jj = 0; jj < cnt; jj++) {
        int j = g_members[off + jj];
        if (j == i) continue;
        uint4 u = *reinterpret_cast<const uint4*>(g_xb + (size_t)j * ND + tid * 8);
        const __nv_bfloat162* p = reinterpret_cast<const __nv_bfloat162*>(&u);
        float acc = 0.f;
        #pragma unroll
        for (int e = 0; e < 4; e++) {
            float2 f = __bfloat1622float2(p[e]);
            acc = fmaf(xi[e * 2], f.x, acc);
            acc = fmaf(xi[e * 2 + 1], f.y, acc);
        }
        #pragma unroll
        for (int o = 16; o; o >>= 1) acc += __shfl_xor_sync(0xffffffffu, acc, o);
        if (lane == 0) wsum[wid] = acc;
        __syncthreads();
        if (tid == 0) {
            float s = wsum[0] + wsum[1] + wsum[2] + wsum[3];
            float lp = -fmaxf(1.25f - s, 0.f) * (s - 0.75f) * 64.f;
            if (np < 256) lp_list[np] = lp;
            np++;
            negfix += __expf(fmaxf(s + 0.25f, 0.f) * (s - 0.25f) * 64.f - 60.f);
        }
        __syncthreads();
    }
    if (tid == 0) {
        int n = np > 256 ? 256 : np;
        float m = -1e30f;
        for (int a = 0; a < n; a++) m = fmaxf(m, lp_list[a]);
        float ssum = 0.f;
        for (int a = 0; a < n; a++) ssum += __expf(lp_list[a] - m);
        g_lsep[i] = m + logf(ssum);
        g_negfix[i] = negfix;
        g_valid[i] = 1;
    }
}

// ---------------------------------------------------------------------------
// Kernel 6: per-row combine, softplus.
// ---------------------------------------------------------------------------
__global__ __launch_bounds__(256) void rowlse_k() {
    int row = blockIdx.x * 256 + threadIdx.x;
    float sn = 0.f;
    #pragma unroll 16
    for (int k = 0; k < NT; k++) sn += g_part_n[(size_t)row * NT + k];
    sn -= g_negfix[row];
    float loss = 0.f;
    if (g_valid[row]) {
        sn = fmaxf(sn, 1e-37f);
        float x = 60.f + logf(sn) + g_lsep[row];
        loss = fmaxf(x, 0.f) + log1pf(expf(-fabsf(x)));
    }
    g_loss[row] = loss;
}

// ---------------------------------------------------------------------------
// Kernel 7: deterministic final reduction.
// ---------------------------------------------------------------------------
__global__ __launch_bounds__(1024) void finalize_k(float* __restrict__ out) {
    __shared__ float sh_s[1024];
    __shared__ int sh_c[1024];
    int tid = threadIdx.x;
    float t = 0.f;
    int c = 0;
    for (int r = tid; r < NB; r += 1024) {
        t += g_loss[r];
        c += g_valid[r];
    }
    sh_s[tid] = t; sh_c[tid] = c;
    __syncthreads();
    for (int off = 512; off > 0; off >>= 1) {
        if (tid < off) {
            sh_s[tid] += sh_s[tid + off];
            sh_c[tid] += sh_c[tid + off];
        }
        __syncthreads();
    }
    if (tid == 0) {
        int cnt = sh_c[0] > 1 ? sh_c[0] : 1;
        out[0] = sh_s[0] / (float)cnt;
    }
}

// ---------------------------------------------------------------------------
extern "C" void kernel_launch(void* const* d_in, const int* in_sizes, int n_in,
                              void* d_out, int out_size) {
    const float* x = (const float*)d_in[0];
    const void* tg = d_in[1];
    float* out = (float*)d_out;

    detect_k<<<1, 512>>>((const int*)tg);
    normalize_k<<<NB, 256>>>(x, tg);
    prefix_k<<<1, 512>>>();
    members_k<<<512, 256>>>();
    gemm_k<<<dim3(NT, NT), 256>>>();
    pos_k<<<NB, 128>>>();
    rowlse_k<<<NB / 256, 256>>>();
    finalize_k<<<1, 1024>>>(out);
}